// round 7
// baseline (speedup 1.0000x reference)
#include <cuda_runtime.h>
#include <cuda_fp16.h>
#include <cuda_bf16.h>
#include <cstdint>

// RGCN: out[i] = x[i]@root + bias + sum_r mean_{j in N_r(i)} x[j] @ W[r]
// Transform-first: y = x @ [W_0..W_7 | root], then per-node slot-list gather.
// R5 theory, third submission (two prior runs died to container infra
// failures, never measured): relation part of y stored fp16 (102 MB ->
// L2-resident; gather traffic halved). Root part fp32. HMMA bf16 split-GEMM.

#define N_NODES 100000
#define N_EDGES_MAX 3200000
#define F 64
#define R 8
#define CAP 192
#define TILES_M 782           // ceil(100000/128)
#define NT 9                  // 8 relations + root

// ---- device scratch ----
__device__ __half g_yrel[(size_t)N_NODES * 512];   // ~102 MB, [node][r][64] fp16
__device__ float  g_yroot[(size_t)N_NODES * 64];   // ~25.6 MB
__device__ int    g_slot[(size_t)N_NODES * CAP];
__device__ int    g_cursor[N_NODES];
__device__ int    g_idx32;
// pre-split W/root, [k][n] bf16, SW128-swizzled byte layout
__device__ __align__(16) unsigned char g_wh[NT * 8192];
__device__ __align__(16) unsigned char g_wl[NT * 8192];

// ================= helpers =================
__device__ __forceinline__ uint32_t sw128(uint32_t off) {
    return off ^ ((off >> 3) & 0x70);
}
__device__ __forceinline__ uint32_t smem_u32(const void* p) {
    uint32_t a;
    asm("{ .reg .u64 t; cvta.to.shared.u64 t, %1; cvt.u32.u64 %0, t; }"
        : "=r"(a) : "l"(p));
    return a;
}
__device__ __forceinline__ void ldm_x4(uint32_t* r, uint32_t addr) {
    asm volatile("ldmatrix.sync.aligned.m8n8.x4.shared.b16 {%0,%1,%2,%3}, [%4];"
        : "=r"(r[0]), "=r"(r[1]), "=r"(r[2]), "=r"(r[3]) : "r"(addr));
}
__device__ __forceinline__ void ldm_x4_t(uint32_t* r, uint32_t addr) {
    asm volatile("ldmatrix.sync.aligned.m8n8.x4.trans.shared.b16 {%0,%1,%2,%3}, [%4];"
        : "=r"(r[0]), "=r"(r[1]), "=r"(r[2]), "=r"(r[3]) : "r"(addr));
}
__device__ __forceinline__ void mma16816(float* c, const uint32_t* a,
                                         const uint32_t* b) {
    asm volatile(
        "mma.sync.aligned.m16n8k16.row.col.f32.bf16.bf16.f32 "
        "{%0,%1,%2,%3}, {%4,%5,%6,%7}, {%8,%9}, {%0,%1,%2,%3};"
        : "+f"(c[0]), "+f"(c[1]), "+f"(c[2]), "+f"(c[3])
        : "r"(a[0]), "r"(a[1]), "r"(a[2]), "r"(a[3]), "r"(b[0]), "r"(b[1]));
}

// ================= prep / binning =================
__global__ void k_zero() {
    int i = blockIdx.x * blockDim.x + threadIdx.x;
    if (i < N_NODES) g_cursor[i] = 0;
    if (i == 0) g_idx32 = 0;
}

__global__ void k_detect(const void* __restrict__ ei, int n_check) {
    int i = threadIdx.x;
    const long long* p = (const long long*)ei;
    int bad = 0;
    for (int e = i; e < n_check; e += blockDim.x) {
        long long v = p[e];
        if (v < 0 || v >= N_NODES) bad = 1;
    }
    if (bad) atomicOr(&g_idx32, 1);
}

__global__ void k_bin(const void* __restrict__ ei_raw,
                      const void* __restrict__ et_raw, int E) {
    int e = blockIdx.x * blockDim.x + threadIdx.x;
    if (e >= E) return;
    int src, dst, r;
    if (g_idx32) {
        const int* ei = (const int*)ei_raw;
        const int* et = (const int*)et_raw;
        src = ei[e]; dst = ei[E + e]; r = et[e];
    } else {
        const long long* ei = (const long long*)ei_raw;
        const long long* et = (const long long*)et_raw;
        src = (int)ei[e]; dst = (int)ei[E + e]; r = (int)et[e];
    }
    if (dst < 0 || dst >= N_NODES) return;
    int pos = atomicAdd(&g_cursor[dst], 1);
    if (pos < CAP) g_slot[(size_t)dst * CAP + pos] = src | (r << 20);
}

// Split W (and root) into (hi, lo) bf16, [k][n] rows (128B), SW128-swizzled.
__global__ void k_split_w(const float* __restrict__ w,
                          const float* __restrict__ root) {
    int nt = blockIdx.x;
    const float* B = (nt < 8) ? (w + (size_t)nt * 4096) : root;
    for (int i = threadIdx.x; i < 4096; i += blockDim.x) {
        int k = i >> 6, n = i & 63;
        float f = B[i];                      // B is [k][n] row-major already
        __nv_bfloat16 h = __float2bfloat16(f);
        __nv_bfloat16 l = __float2bfloat16(f - __bfloat162float(h));
        uint32_t off = sw128((uint32_t)(k * 128 + n * 2));
        *(__nv_bfloat16*)(g_wh + nt * 8192 + off) = h;
        *(__nv_bfloat16*)(g_wl + nt * 8192 + off) = l;
    }
}

// ================= HMMA GEMM =================
// Block: 128-row tile, 8 warps (warp = 16 rows x 64 cols), loop over 9 nt.
__global__ __launch_bounds__(256, 2) void k_gemm(const float* __restrict__ x) {
    __shared__ __align__(1024) unsigned char sAh[16384];
    __shared__ __align__(1024) unsigned char sAl[16384];
    __shared__ __align__(1024) unsigned char sBh[8192];
    __shared__ __align__(1024) unsigned char sBl[8192];

    int tid = threadIdx.x, lane = tid & 31, wid = tid >> 5;
    int m_base = blockIdx.x * 128;

    // ---- split x tile -> (hi, lo) bf16 SMEM, SW128 swizzled ----
    for (int i = tid; i < 1024; i += 256) {
        int row = i >> 3, c8 = i & 7;
        int gm = m_base + row;
        float f[8];
        if (gm < N_NODES) {
            const float4* xr = (const float4*)(x + (size_t)gm * F);
            float4 v0 = xr[c8 * 2], v1 = xr[c8 * 2 + 1];
            f[0] = v0.x; f[1] = v0.y; f[2] = v0.z; f[3] = v0.w;
            f[4] = v1.x; f[5] = v1.y; f[6] = v1.z; f[7] = v1.w;
        } else {
            #pragma unroll
            for (int j = 0; j < 8; j++) f[j] = 0.f;
        }
        union { unsigned short u[8]; uint4 v; } hi, lo;
        #pragma unroll
        for (int j = 0; j < 8; j++) {
            __nv_bfloat16 h = __float2bfloat16(f[j]);
            __nv_bfloat16 l = __float2bfloat16(f[j] - __bfloat162float(h));
            hi.u[j] = *(unsigned short*)&h;
            lo.u[j] = *(unsigned short*)&l;
        }
        uint32_t off = sw128((uint32_t)(row * 128 + c8 * 16));
        *(uint4*)(sAh + off) = hi.v;
        *(uint4*)(sAl + off) = lo.v;
    }
    __syncthreads();

    // ---- preload all A fragments (held across the nt loop) ----
    uint32_t Ah[4][4], Al[4][4];
    uint32_t baseAh = smem_u32(sAh), baseAl = smem_u32(sAl);
    int m0 = wid * 16;
    #pragma unroll
    for (int ks = 0; ks < 4; ks++) {
        uint32_t off = sw128((uint32_t)((m0 + (lane & 15)) * 128
                                        + ks * 32 + (lane >> 4) * 16));
        ldm_x4(Ah[ks], baseAh + off);
        ldm_x4(Al[ks], baseAl + off);
    }

    uint32_t baseBh = smem_u32(sBh), baseBl = smem_u32(sBl);

    for (int nt = 0; nt < NT; nt++) {
        __syncthreads();   // previous nt's B-frag loads done before overwrite
        {
            const uint4* sh = (const uint4*)(g_wh + nt * 8192);
            const uint4* sl = (const uint4*)(g_wl + nt * 8192);
            uint4* dh = (uint4*)sBh;
            uint4* dl = (uint4*)sBl;
            #pragma unroll
            for (int i = 0; i < 2; i++) {
                dh[tid + i * 256] = sh[tid + i * 256];
                dl[tid + i * 256] = sl[tid + i * 256];
            }
        }
        __syncthreads();

        float acc[8][4];
        #pragma unroll
        for (int t = 0; t < 8; t++)
            #pragma unroll
            for (int c = 0; c < 4; c++) acc[t][c] = 0.f;

        #pragma unroll
        for (int ks = 0; ks < 4; ks++) {
            uint32_t boff[4];
            #pragma unroll
            for (int np = 0; np < 4; np++)
                boff[np] = sw128((uint32_t)((ks * 16 + (lane & 15)) * 128
                                            + (np * 16 + (lane >> 4) * 8) * 2));
            uint32_t b[4][4];
            #pragma unroll
            for (int np = 0; np < 4; np++) ldm_x4_t(b[np], baseBh + boff[np]);
            #pragma unroll
            for (int np = 0; np < 4; np++) {
                mma16816(acc[2 * np],     Ah[ks], &b[np][0]);
                mma16816(acc[2 * np + 1], Ah[ks], &b[np][2]);
                mma16816(acc[2 * np],     Al[ks], &b[np][0]);
                mma16816(acc[2 * np + 1], Al[ks], &b[np][2]);
            }
            #pragma unroll
            for (int np = 0; np < 4; np++) ldm_x4_t(b[np], baseBl + boff[np]);
            #pragma unroll
            for (int np = 0; np < 4; np++) {
                mma16816(acc[2 * np],     Ah[ks], &b[np][0]);
                mma16816(acc[2 * np + 1], Ah[ks], &b[np][2]);
            }
        }

        // ---- epilogue: rows lane>>2 and lane>>2 + 8, col pair (lane&3)*2 ----
        int gm0 = m_base + m0 + (lane >> 2);
        if (nt < 8) {
            #pragma unroll
            for (int t = 0; t < 8; t++) {
                int col = nt * 64 + t * 8 + (lane & 3) * 2;
                __half2* d0 = (__half2*)(g_yrel + (size_t)gm0 * 512 + col);
                if (gm0 < N_NODES)
                    *d0 = __floats2half2_rn(acc[t][0], acc[t][1]);
                if (gm0 + 8 < N_NODES)
                    *(__half2*)((__half*)d0 + 8 * 512)
                        = __floats2half2_rn(acc[t][2], acc[t][3]);
            }
        } else {
            #pragma unroll
            for (int t = 0; t < 8; t++) {
                float* d0 = g_yroot + (size_t)gm0 * 64 + t * 8 + (lane & 3) * 2;
                if (gm0 < N_NODES)
                    *(float2*)d0 = make_float2(acc[t][0], acc[t][1]);
                if (gm0 + 8 < N_NODES)
                    *(float2*)(d0 + 8 * 64) = make_float2(acc[t][2], acc[t][3]);
            }
        }
    }
}

// ================= aggregation =================
// One warp per node; lane owns features (2*lane, 2*lane+1) -> one half2/edge.
__global__ __launch_bounds__(256) void k_agg(const float* __restrict__ bias,
                                             float* __restrict__ out) {
    int wib  = threadIdx.x >> 5;
    int lane = threadIdx.x & 31;
    int node = blockIdx.x * 8 + wib;
    if (node >= N_NODES) return;

    float2 br = *(const float2*)(bias + lane * 2);
    float2 rr = *(const float2*)(g_yroot + (size_t)node * 64 + lane * 2);
    float acc0 = rr.x + br.x;
    float acc1 = rr.y + br.y;

    int deg = g_cursor[node];
    if (deg > CAP) deg = CAP;
    const int* sl = g_slot + (size_t)node * CAP;

    unsigned long long pc = 0;
    for (int e = lane; e < deg; e += 32)
        pc += 1ULL << ((((unsigned)sl[e]) >> 20) * 8);
    #pragma unroll
    for (int o = 16; o; o >>= 1) pc += __shfl_xor_sync(0xffffffffu, pc, o);
    float inv = 1.0f;
    if (lane < R) {
        int c = (int)((pc >> (lane * 8)) & 0xFF);
        inv = 1.0f / (float)(c > 0 ? c : 1);
    }

    const __half2* yb = (const __half2*)g_yrel;
    int e = 0;
    for (; e + 8 <= deg; e += 8) {
        int p[8];
        #pragma unroll
        for (int j = 0; j < 8; j++) p[j] = sl[e + j];
        __half2 h[8];
        float w[8];
        #pragma unroll
        for (int j = 0; j < 8; j++) {
            unsigned pk = (unsigned)p[j];
            h[j] = yb[(size_t)(pk & 0xFFFFF) * 256 + (pk >> 20) * 32 + lane];
            w[j] = __shfl_sync(0xffffffffu, inv, pk >> 20);
        }
        #pragma unroll
        for (int j = 0; j < 8; j++) {
            float2 v = __half22float2(h[j]);
            acc0 += w[j] * v.x;
            acc1 += w[j] * v.y;
        }
    }
    for (; e < deg; e++) {
        unsigned pk = (unsigned)sl[e];
        float2 v = __half22float2(
            yb[(size_t)(pk & 0xFFFFF) * 256 + (pk >> 20) * 32 + lane]);
        float w = __shfl_sync(0xffffffffu, inv, pk >> 20);
        acc0 += w * v.x;
        acc1 += w * v.y;
    }

    *(float2*)(out + (size_t)node * F + lane * 2) = make_float2(acc0, acc1);
}

// ---------------------------------------------------------------
extern "C" void kernel_launch(void* const* d_in, const int* in_sizes, int n_in,
                              void* d_out, int out_size) {
    const float* x    = (const float*)d_in[0];
    const void*  ei   = d_in[1];
    const void*  et   = d_in[2];
    const float* w    = (const float*)d_in[3];
    const float* root = (const float*)d_in[4];
    const float* bias = (const float*)d_in[5];
    float* out = (float*)d_out;

    int E = in_sizes[2];
    if (E > N_EDGES_MAX) E = N_EDGES_MAX;
    int n_check = E < 1024 ? E : 1024;

    k_zero<<<(N_NODES + 255) / 256, 256>>>();
    k_detect<<<1, 256>>>(ei, n_check);
    k_bin<<<(E + 255) / 256, 256>>>(ei, et, E);
    k_split_w<<<NT, 256>>>(w, root);
    k_gemm<<<TILES_M, 256>>>(x);
    k_agg<<<(N_NODES + 7) / 8, 256>>>(bias, out);
}

// round 8
// speedup vs baseline: 1.2404x; 1.2404x over previous
#include <cuda_runtime.h>
#include <cuda_fp16.h>
#include <cuda_bf16.h>
#include <cstdint>

// RGCN: out[i] = x[i]@root + bias + sum_r mean_{j in N_r(i)} x[j] @ W[r]
// Transform-first: y = x @ [W_0..W_7 | root], then per-node slot-list gather.
// R8: fp16 relation-y kept, but (a) agg processes 2 edges/warp with 8B lanes
// (2x MLP, coalesced 128B lines), (b) gemm epilogue staged through SMEM for
// 128B-coalesced fp16 row writes.

#define N_NODES 100000
#define N_EDGES_MAX 3200000
#define F 64
#define R 8
#define CAP 192
#define TILES_M 782           // ceil(100000/128)
#define NT 9                  // 8 relations + root

// ---- device scratch ----
__device__ __half g_yrel[(size_t)N_NODES * 512];   // ~102 MB, [node][r][64] fp16
__device__ float  g_yroot[(size_t)N_NODES * 64];   // ~25.6 MB
__device__ int    g_slot[(size_t)N_NODES * CAP];
__device__ int    g_cursor[N_NODES];
__device__ int    g_idx32;
// pre-split W/root, [k][n] bf16, SW128-swizzled byte layout
__device__ __align__(16) unsigned char g_wh[NT * 8192];
__device__ __align__(16) unsigned char g_wl[NT * 8192];

// ================= helpers =================
__device__ __forceinline__ uint32_t sw128(uint32_t off) {
    return off ^ ((off >> 3) & 0x70);
}
__device__ __forceinline__ uint32_t smem_u32(const void* p) {
    uint32_t a;
    asm("{ .reg .u64 t; cvta.to.shared.u64 t, %1; cvt.u32.u64 %0, t; }"
        : "=r"(a) : "l"(p));
    return a;
}
__device__ __forceinline__ void ldm_x4(uint32_t* r, uint32_t addr) {
    asm volatile("ldmatrix.sync.aligned.m8n8.x4.shared.b16 {%0,%1,%2,%3}, [%4];"
        : "=r"(r[0]), "=r"(r[1]), "=r"(r[2]), "=r"(r[3]) : "r"(addr));
}
__device__ __forceinline__ void ldm_x4_t(uint32_t* r, uint32_t addr) {
    asm volatile("ldmatrix.sync.aligned.m8n8.x4.trans.shared.b16 {%0,%1,%2,%3}, [%4];"
        : "=r"(r[0]), "=r"(r[1]), "=r"(r[2]), "=r"(r[3]) : "r"(addr));
}
__device__ __forceinline__ void mma16816(float* c, const uint32_t* a,
                                         const uint32_t* b) {
    asm volatile(
        "mma.sync.aligned.m16n8k16.row.col.f32.bf16.bf16.f32 "
        "{%0,%1,%2,%3}, {%4,%5,%6,%7}, {%8,%9}, {%0,%1,%2,%3};"
        : "+f"(c[0]), "+f"(c[1]), "+f"(c[2]), "+f"(c[3])
        : "r"(a[0]), "r"(a[1]), "r"(a[2]), "r"(a[3]), "r"(b[0]), "r"(b[1]));
}

// ================= prep / binning =================
__global__ void k_zero() {
    int i = blockIdx.x * blockDim.x + threadIdx.x;
    if (i < N_NODES) g_cursor[i] = 0;
    if (i == 0) g_idx32 = 0;
}

__global__ void k_detect(const void* __restrict__ ei, int n_check) {
    int i = threadIdx.x;
    const long long* p = (const long long*)ei;
    int bad = 0;
    for (int e = i; e < n_check; e += blockDim.x) {
        long long v = p[e];
        if (v < 0 || v >= N_NODES) bad = 1;
    }
    if (bad) atomicOr(&g_idx32, 1);
}

__global__ void k_bin(const void* __restrict__ ei_raw,
                      const void* __restrict__ et_raw, int E) {
    int e = blockIdx.x * blockDim.x + threadIdx.x;
    if (e >= E) return;
    int src, dst, r;
    if (g_idx32) {
        const int* ei = (const int*)ei_raw;
        const int* et = (const int*)et_raw;
        src = ei[e]; dst = ei[E + e]; r = et[e];
    } else {
        const long long* ei = (const long long*)ei_raw;
        const long long* et = (const long long*)et_raw;
        src = (int)ei[e]; dst = (int)ei[E + e]; r = (int)et[e];
    }
    if (dst < 0 || dst >= N_NODES) return;
    int pos = atomicAdd(&g_cursor[dst], 1);
    if (pos < CAP) g_slot[(size_t)dst * CAP + pos] = src | (r << 20);
}

// Split W (and root) into (hi, lo) bf16, [k][n] rows (128B), SW128-swizzled.
__global__ void k_split_w(const float* __restrict__ w,
                          const float* __restrict__ root) {
    int nt = blockIdx.x;
    const float* B = (nt < 8) ? (w + (size_t)nt * 4096) : root;
    for (int i = threadIdx.x; i < 4096; i += blockDim.x) {
        int k = i >> 6, n = i & 63;
        float f = B[i];
        __nv_bfloat16 h = __float2bfloat16(f);
        __nv_bfloat16 l = __float2bfloat16(f - __bfloat162float(h));
        uint32_t off = sw128((uint32_t)(k * 128 + n * 2));
        *(__nv_bfloat16*)(g_wh + nt * 8192 + off) = h;
        *(__nv_bfloat16*)(g_wl + nt * 8192 + off) = l;
    }
}

// ================= HMMA GEMM =================
// Block: 128-row tile, 8 warps (warp = 16 rows x 64 cols), loop over 9 nt.
// fp16 epilogue staged through SMEM (reuses sAh) for coalesced 128B writes.
__global__ __launch_bounds__(256, 2) void k_gemm(const float* __restrict__ x) {
    __shared__ __align__(1024) unsigned char sAh[16384];
    __shared__ __align__(1024) unsigned char sAl[16384];
    __shared__ __align__(1024) unsigned char sBh[8192];
    __shared__ __align__(1024) unsigned char sBl[8192];

    int tid = threadIdx.x, lane = tid & 31, wid = tid >> 5;
    int m_base = blockIdx.x * 128;

    // ---- split x tile -> (hi, lo) bf16 SMEM, SW128 swizzled ----
    for (int i = tid; i < 1024; i += 256) {
        int row = i >> 3, c8 = i & 7;
        int gm = m_base + row;
        float f[8];
        if (gm < N_NODES) {
            const float4* xr = (const float4*)(x + (size_t)gm * F);
            float4 v0 = xr[c8 * 2], v1 = xr[c8 * 2 + 1];
            f[0] = v0.x; f[1] = v0.y; f[2] = v0.z; f[3] = v0.w;
            f[4] = v1.x; f[5] = v1.y; f[6] = v1.z; f[7] = v1.w;
        } else {
            #pragma unroll
            for (int j = 0; j < 8; j++) f[j] = 0.f;
        }
        union { unsigned short u[8]; uint4 v; } hi, lo;
        #pragma unroll
        for (int j = 0; j < 8; j++) {
            __nv_bfloat16 h = __float2bfloat16(f[j]);
            __nv_bfloat16 l = __float2bfloat16(f[j] - __bfloat162float(h));
            hi.u[j] = *(unsigned short*)&h;
            lo.u[j] = *(unsigned short*)&l;
        }
        uint32_t off = sw128((uint32_t)(row * 128 + c8 * 16));
        *(uint4*)(sAh + off) = hi.v;
        *(uint4*)(sAl + off) = lo.v;
    }
    __syncthreads();

    // ---- preload all A fragments (held in registers across the nt loop) ----
    uint32_t Ah[4][4], Al[4][4];
    uint32_t baseAh = smem_u32(sAh), baseAl = smem_u32(sAl);
    int m0 = wid * 16;
    #pragma unroll
    for (int ks = 0; ks < 4; ks++) {
        uint32_t off = sw128((uint32_t)((m0 + (lane & 15)) * 128
                                        + ks * 32 + (lane >> 4) * 16));
        ldm_x4(Ah[ks], baseAh + off);
        ldm_x4(Al[ks], baseAl + off);
    }

    uint32_t baseBh = smem_u32(sBh), baseBl = smem_u32(sBl);
    __half* stage = (__half*)sAh;   // 128 x 64 fp16 = 16 KB (sAh dead now)

    for (int nt = 0; nt < NT; nt++) {
        __syncthreads();   // prior iter's reads (B frags, stage copy-out) done
        {
            const uint4* sh = (const uint4*)(g_wh + nt * 8192);
            const uint4* sl = (const uint4*)(g_wl + nt * 8192);
            uint4* dh = (uint4*)sBh;
            uint4* dl = (uint4*)sBl;
            #pragma unroll
            for (int i = 0; i < 2; i++) {
                dh[tid + i * 256] = sh[tid + i * 256];
                dl[tid + i * 256] = sl[tid + i * 256];
            }
        }
        __syncthreads();

        float acc[8][4];
        #pragma unroll
        for (int t = 0; t < 8; t++)
            #pragma unroll
            for (int c = 0; c < 4; c++) acc[t][c] = 0.f;

        #pragma unroll
        for (int ks = 0; ks < 4; ks++) {
            uint32_t boff[4];
            #pragma unroll
            for (int np = 0; np < 4; np++)
                boff[np] = sw128((uint32_t)((ks * 16 + (lane & 15)) * 128
                                            + (np * 16 + (lane >> 4) * 8) * 2));
            uint32_t b[4][4];
            #pragma unroll
            for (int np = 0; np < 4; np++) ldm_x4_t(b[np], baseBh + boff[np]);
            #pragma unroll
            for (int np = 0; np < 4; np++) {
                mma16816(acc[2 * np],     Ah[ks], &b[np][0]);
                mma16816(acc[2 * np + 1], Ah[ks], &b[np][2]);
                mma16816(acc[2 * np],     Al[ks], &b[np][0]);
                mma16816(acc[2 * np + 1], Al[ks], &b[np][2]);
            }
            #pragma unroll
            for (int np = 0; np < 4; np++) ldm_x4_t(b[np], baseBl + boff[np]);
            #pragma unroll
            for (int np = 0; np < 4; np++) {
                mma16816(acc[2 * np],     Ah[ks], &b[np][0]);
                mma16816(acc[2 * np + 1], Ah[ks], &b[np][2]);
            }
        }

        if (nt < 8) {
            // stage fp16 tile in SMEM, then coalesced 128B row writes
            int r0 = m0 + (lane >> 2);
            #pragma unroll
            for (int t = 0; t < 8; t++) {
                int col = t * 8 + (lane & 3) * 2;
                *(__half2*)(stage + r0 * 64 + col)
                    = __floats2half2_rn(acc[t][0], acc[t][1]);
                *(__half2*)(stage + (r0 + 8) * 64 + col)
                    = __floats2half2_rn(acc[t][2], acc[t][3]);
            }
            __syncthreads();
            // copy out: 1024 uint4, thread i -> row i>>3, chunk i&7
            const uint4* ss = (const uint4*)stage;
            #pragma unroll
            for (int i = 0; i < 4; i++) {
                int idx = tid + i * 256;
                int row = idx >> 3, c = idx & 7;
                int gm = m_base + row;
                if (gm < N_NODES)
                    ((uint4*)g_yrel)[(size_t)gm * 64 + nt * 8 + c] = ss[idx];
            }
        } else {
            int gm0 = m_base + m0 + (lane >> 2);
            #pragma unroll
            for (int t = 0; t < 8; t++) {
                float* d0 = g_yroot + (size_t)gm0 * 64 + t * 8 + (lane & 3) * 2;
                if (gm0 < N_NODES)
                    *(float2*)d0 = make_float2(acc[t][0], acc[t][1]);
                if (gm0 + 8 < N_NODES)
                    *(float2*)(d0 + 8 * 64) = make_float2(acc[t][2], acc[t][3]);
            }
        }
    }
}

// ================= aggregation =================
// One warp per node, TWO edges in flight per iteration:
// lanes 0-15 take even edges, 16-31 odd. Lane loads uint2 = 4 fp16 feats
// (feats q*4..q*4+3, q = lane&15); 16 lanes cover the full 128B row.
// Final shfl_xor(16) combines the two edge streams.
__global__ __launch_bounds__(256) void k_agg(const float* __restrict__ bias,
                                             float* __restrict__ out) {
    int wib  = threadIdx.x >> 5;
    int lane = threadIdx.x & 31;
    int node = blockIdx.x * 8 + wib;
    if (node >= N_NODES) return;
    int half = lane >> 4, q = lane & 15;

    int deg = g_cursor[node];
    if (deg > CAP) deg = CAP;
    const int* sl = g_slot + (size_t)node * CAP;

    // per-relation counts (packed 8x8-bit)
    unsigned long long pc = 0;
    for (int e = lane; e < deg; e += 32)
        pc += 1ULL << ((((unsigned)sl[e]) >> 20) * 8);
    #pragma unroll
    for (int o = 16; o; o >>= 1) pc += __shfl_xor_sync(0xffffffffu, pc, o);
    float inv = 1.0f;
    if (lane < R) {
        int c = (int)((pc >> (lane * 8)) & 0xFF);
        inv = 1.0f / (float)(c > 0 ? c : 1);
    }

    float a0 = 0.f, a1 = 0.f, a2 = 0.f, a3 = 0.f;
    const uint2* yb = (const uint2*)g_yrel;

    int e = 0;
    for (; e + 16 <= deg; e += 16) {
        int p[8];
        #pragma unroll
        for (int j = 0; j < 8; j++) p[j] = sl[e + 2 * j + half];
        uint2 v[8];
        float w[8];
        #pragma unroll
        for (int j = 0; j < 8; j++) {
            unsigned pk = (unsigned)p[j];
            v[j] = yb[(size_t)(pk & 0xFFFFF) * 128 + (pk >> 20) * 16 + q];
            w[j] = __shfl_sync(0xffffffffu, inv, pk >> 20);
        }
        #pragma unroll
        for (int j = 0; j < 8; j++) {
            float2 f0 = __half22float2(*(__half2*)&v[j].x);
            float2 f1 = __half22float2(*(__half2*)&v[j].y);
            a0 += w[j] * f0.x; a1 += w[j] * f0.y;
            a2 += w[j] * f1.x; a3 += w[j] * f1.y;
        }
    }
    for (; e + 2 <= deg; e += 2) {
        unsigned pk = (unsigned)sl[e + half];
        uint2 v = yb[(size_t)(pk & 0xFFFFF) * 128 + (pk >> 20) * 16 + q];
        float w = __shfl_sync(0xffffffffu, inv, pk >> 20);
        float2 f0 = __half22float2(*(__half2*)&v.x);
        float2 f1 = __half22float2(*(__half2*)&v.y);
        a0 += w * f0.x; a1 += w * f0.y;
        a2 += w * f1.x; a3 += w * f1.y;
    }
    if (e < deg) {                      // odd tail edge: half 0 only
        unsigned pk = (unsigned)sl[e];
        float w = __shfl_sync(0xffffffffu, inv, pk >> 20);
        if (half == 0) {
            uint2 v = yb[(size_t)(pk & 0xFFFFF) * 128 + (pk >> 20) * 16 + q];
            float2 f0 = __half22float2(*(__half2*)&v.x);
            float2 f1 = __half22float2(*(__half2*)&v.y);
            a0 += w * f0.x; a1 += w * f0.y;
            a2 += w * f1.x; a3 += w * f1.y;
        }
    }

    // combine the two edge streams
    a0 += __shfl_xor_sync(0xffffffffu, a0, 16);
    a1 += __shfl_xor_sync(0xffffffffu, a1, 16);
    a2 += __shfl_xor_sync(0xffffffffu, a2, 16);
    a3 += __shfl_xor_sync(0xffffffffu, a3, 16);

    if (half == 0) {
        float4 rb = *(const float4*)(g_yroot + (size_t)node * 64 + q * 4);
        float4 bs = *(const float4*)(bias + q * 4);
        float4 o = make_float4(a0 + rb.x + bs.x, a1 + rb.y + bs.y,
                               a2 + rb.z + bs.z, a3 + rb.w + bs.w);
        *(float4*)(out + (size_t)node * F + q * 4) = o;
    }
}

// ---------------------------------------------------------------
extern "C" void kernel_launch(void* const* d_in, const int* in_sizes, int n_in,
                              void* d_out, int out_size) {
    const float* x    = (const float*)d_in[0];
    const void*  ei   = d_in[1];
    const void*  et   = d_in[2];
    const float* w    = (const float*)d_in[3];
    const float* root = (const float*)d_in[4];
    const float* bias = (const float*)d_in[5];
    float* out = (float*)d_out;

    int E = in_sizes[2];
    if (E > N_EDGES_MAX) E = N_EDGES_MAX;
    int n_check = E < 1024 ? E : 1024;

    k_zero<<<(N_NODES + 255) / 256, 256>>>();
    k_detect<<<1, 256>>>(ei, n_check);
    k_bin<<<(E + 255) / 256, 256>>>(ei, et, E);
    k_split_w<<<NT, 256>>>(w, root);
    k_gemm<<<TILES_M, 256>>>(x);
    k_agg<<<(N_NODES + 7) / 8, 256>>>(bias, out);
}